// round 2
// baseline (speedup 1.0000x reference)
#include <cuda_runtime.h>

#define FULLMASK 0xffffffffu
#define C_IN 32
#define C_OUT 64
#define K_TAPS 8
#define NMAX 2001024

// ---------------- device scratch (no allocation allowed) ----------------
__device__ float g_sum[C_IN];
__device__ float g_sq[C_IN];
__device__ float g_scale[C_IN];
__device__ float g_shift[C_IN];
__device__ int   g_hist[K_TAPS];
__device__ int   g_base[K_TAPS + 1];
__device__ int   g_cursor[K_TAPS];
__device__ int   g_perm[NMAX];

// ---------------- small PTX helpers ----------------
__device__ __forceinline__ unsigned long long fma2(unsigned long long a,
                                                   unsigned long long b,
                                                   unsigned long long c) {
    unsigned long long d;
    asm("fma.rn.f32x2 %0, %1, %2, %3;" : "=l"(d) : "l"(a), "l"(b), "l"(c));
    return d;
}

__device__ __forceinline__ void red_add_v2(float* p, float a, float b) {
    asm volatile("red.global.add.v2.f32 [%0], {%1, %2};"
                 :: "l"(p), "f"(a), "f"(b) : "memory");
}

// ---------------- kernels ----------------
__global__ void k_init() {
    int t = threadIdx.x;
    if (t < C_IN) { g_sum[t] = 0.f; g_sq[t] = 0.f; }
    if (t < K_TAPS) g_hist[t] = 0;
}

__global__ void k_zero_out(float4* out, long n4) {
    long i = blockIdx.x * (long)blockDim.x + threadIdx.x;
    long stride = (long)gridDim.x * blockDim.x;
    float4 z = make_float4(0.f, 0.f, 0.f, 0.f);
    for (; i < n4; i += stride) out[i] = z;
}

__global__ void k_stats(const float* __restrict__ f, long total) {
    long i = blockIdx.x * (long)blockDim.x + threadIdx.x;
    long stride = (long)gridDim.x * blockDim.x;   // multiple of 32
    float s = 0.f, q = 0.f;
    for (; i < total; i += stride) {
        float x = f[i];
        s += x;
        q = fmaf(x, x, q);
    }
    __shared__ float ss[C_IN], sq[C_IN];
    int t = threadIdx.x;
    if (t < C_IN) { ss[t] = 0.f; sq[t] = 0.f; }
    __syncthreads();
    int c = t & 31;
    atomicAdd(&ss[c], s);
    atomicAdd(&sq[c], q);
    __syncthreads();
    if (t < C_IN) {
        atomicAdd(&g_sum[t], ss[t]);
        atomicAdd(&g_sq[t], sq[t]);
    }
}

__global__ void k_finalize(const float* __restrict__ gamma,
                           const float* __restrict__ beta, float inv_n) {
    int c = threadIdx.x;
    if (c < C_IN) {
        float mean = g_sum[c] * inv_n;
        float var  = g_sq[c] * inv_n - mean * mean;
        float sc   = gamma[c] * rsqrtf(var + 1e-5f);
        g_scale[c] = sc;
        g_shift[c] = beta[c] - mean * sc;
    }
}

__global__ void k_hist(const int* __restrict__ off, int n) {
    __shared__ int h[K_TAPS];
    if (threadIdx.x < K_TAPS) h[threadIdx.x] = 0;
    __syncthreads();
    int i = blockIdx.x * blockDim.x + threadIdx.x;
    int stride = gridDim.x * blockDim.x;
    for (; i < n; i += stride) atomicAdd(&h[off[i] & 7], 1);
    __syncthreads();
    if (threadIdx.x < K_TAPS) atomicAdd(&g_hist[threadIdx.x], h[threadIdx.x]);
}

__global__ void k_scan() {
    int acc = 0;
    for (int t = 0; t < K_TAPS; t++) {
        g_base[t] = acc;
        g_cursor[t] = acc;
        acc += g_hist[t];
    }
    g_base[K_TAPS] = acc;
}

__global__ void k_scatter(const int* __restrict__ off, int n) {
    int i = blockIdx.x * blockDim.x + threadIdx.x;
    int stride = gridDim.x * blockDim.x;           // multiple of 32
    int lane = threadIdx.x & 31;
    int nr = ((n + 31) >> 5) << 5;                 // warp-uniform bound
    for (; i < nr; i += stride) {
        bool valid = (i < n);
        unsigned mask = __ballot_sync(FULLMASK, valid);
        if (valid) {
            int tap = off[i] & 7;
            unsigned peers = __match_any_sync(mask, tap);
            int leader = __ffs(peers) - 1;
            unsigned lt = (1u << lane) - 1u;
            int rank = __popc(peers & lt);
            int pos0 = 0;
            if (lane == leader) pos0 = atomicAdd(&g_cursor[tap], __popc(peers));
            pos0 = __shfl_sync(mask, pos0, leader);
            g_perm[pos0 + rank] = i;
        }
    }
}

// Main conv: each warp owns a contiguous chunk of the tap-sorted permutation,
// tap weights live in 32 packed-f32x2 registers per lane (lane -> out cols 2l,2l+1).
__global__ void __launch_bounds__(256)
k_conv(const float* __restrict__ f, const float* __restrict__ weight,
       const int* __restrict__ out_index, float* __restrict__ out,
       int n, int chunk) {
    __shared__ ulonglong2 sv[8][2][16];   // per-warp double-buffered 64-float stage
    int lane = threadIdx.x & 31;
    int wl = threadIdx.x >> 5;
    int w = (blockIdx.x * blockDim.x + threadIdx.x) >> 5;
    long startl = (long)w * chunk;
    if (startl >= n) return;
    int start = (int)startl;
    int end = (int)min((long)n, startl + chunk);

    float sc = g_scale[lane];
    float sh = g_shift[lane];

    int tap = -1;
    int nb = 0;                          // next bin boundary; forces initial load
    unsigned long long wreg[32];

    for (int j = start; j < end; j++) {
        if (j >= nb) {
            do { tap++; nb = g_base[tap + 1]; } while (j >= nb);
            const float* wp = weight + ((tap << 5) << 6) + (lane << 1);
#pragma unroll
            for (int c = 0; c < 32; c++)
                wreg[c] = *(const unsigned long long*)(wp + (c << 6));
        }
        int i = g_perm[j];
        int row = out_index[i];
        float x = f[(i << 5) + lane];
        float v = fmaxf(fmaf(x, sc, sh), 0.f);

        int buf = j & 1;
        float2* svp = (float2*)&sv[wl][buf][0];
        svp[lane] = make_float2(v, v);
        __syncwarp();

        unsigned long long acc = 0ull;   // packed {0.f, 0.f}
        const ulonglong2* vp = (const ulonglong2*)&sv[wl][buf][0];
#pragma unroll
        for (int k = 0; k < 16; k++) {
            ulonglong2 q = vp[k];        // (v2k,v2k | v2k+1,v2k+1) broadcast LDS.128
            acc = fma2(q.x, wreg[2 * k], acc);
            acc = fma2(q.y, wreg[2 * k + 1], acc);
        }
        float rx, ry;
        asm("mov.b64 {%0, %1}, %2;" : "=f"(rx), "=f"(ry) : "l"(acc));
        red_add_v2(out + ((long)row << 6) + (lane << 1), rx, ry);
    }
}

// ---------------- launch ----------------
extern "C" void kernel_launch(void* const* d_in, const int* in_sizes, int n_in,
                              void* d_out, int out_size) {
    const float* features = (const float*)d_in[0];
    const float* gamma    = (const float*)d_in[1];
    const float* beta     = (const float*)d_in[2];
    const float* weight   = (const float*)d_in[3];
    const int* out_index  = (const int*)d_in[4];
    const int* off_index  = (const int*)d_in[5];

    int n = in_sizes[0] / C_IN;

    k_zero_out<<<8192, 256>>>((float4*)d_out, (long)out_size / 4);
    k_init<<<1, 64>>>();
    k_stats<<<1184, 256>>>(features, (long)n * C_IN);
    k_finalize<<<1, 32>>>(gamma, beta, 1.0f / (float)n);
    k_hist<<<1184, 256>>>(off_index, n);
    k_scan<<<1, 1>>>();
    k_scatter<<<1184, 256>>>(off_index, n);

    int warps = 2048 * 8;
    int chunk = (n + warps - 1) / warps;
    if (chunk < 1) chunk = 1;
    k_conv<<<2048, 256>>>(features, weight, out_index, (float*)d_out, n, chunk);
}

// round 3
// speedup vs baseline: 1.5543x; 1.5543x over previous
#include <cuda_runtime.h>

#define FULLMASK 0xffffffffu
#define C_IN 32
#define C_OUT 64
#define K_TAPS 8
#define NMAX 2001024
#define BATCH 8

// ---------------- device scratch (no allocation allowed) ----------------
__device__ float g_sum[C_IN];
__device__ float g_sq[C_IN];
__device__ float g_scale[C_IN];
__device__ float g_shift[C_IN];
__device__ int   g_hist[K_TAPS];
__device__ int   g_base[K_TAPS + 1];
__device__ int   g_cursor[K_TAPS];
__device__ int   g_perm[NMAX];

// ---------------- small PTX helpers ----------------
__device__ __forceinline__ unsigned long long fma2(unsigned long long a,
                                                   unsigned long long b,
                                                   unsigned long long c) {
    unsigned long long d;
    asm("fma.rn.f32x2 %0, %1, %2, %3;" : "=l"(d) : "l"(a), "l"(b), "l"(c));
    return d;
}

__device__ __forceinline__ unsigned long long add2(unsigned long long a,
                                                   unsigned long long b) {
    unsigned long long d;
    asm("add.rn.f32x2 %0, %1, %2;" : "=l"(d) : "l"(a), "l"(b));
    return d;
}

__device__ __forceinline__ void red_add_v2(float* p, float a, float b) {
    asm volatile("red.global.add.v2.f32 [%0], {%1, %2};"
                 :: "l"(p), "f"(a), "f"(b) : "memory");
}

// ---------------- fused: zero d_out + BN stats + tap histogram ----------------
__global__ void __launch_bounds__(256) k_pre(
    float4* __restrict__ out4, long n4,
    const float4* __restrict__ f4, long nf4,
    const int4* __restrict__ off4, int nq, int n) {
    long tid = blockIdx.x * (long)blockDim.x + threadIdx.x;
    long S = (long)gridDim.x * blockDim.x;

    // --- zero output ---
    float4 z = make_float4(0.f, 0.f, 0.f, 0.f);
    for (long i = tid; i < n4; i += S) out4[i] = z;

    // --- stats (each thread owns 4 fixed channels since 4*S % 32 == 0) ---
    float s0 = 0, s1 = 0, s2 = 0, s3 = 0;
    float q0 = 0, q1 = 0, q2 = 0, q3 = 0;
    for (long i = tid; i < nf4; i += S) {
        float4 v = f4[i];
        s0 += v.x; q0 = fmaf(v.x, v.x, q0);
        s1 += v.y; q1 = fmaf(v.y, v.y, q1);
        s2 += v.z; q2 = fmaf(v.z, v.z, q2);
        s3 += v.w; q3 = fmaf(v.w, v.w, q3);
    }
    int c0 = (int)((tid * 4) & 31);

    __shared__ float ss[C_IN], sq[C_IN];
    __shared__ int sh[K_TAPS];
    int t = threadIdx.x;
    if (t < C_IN) { ss[t] = 0.f; sq[t] = 0.f; }
    if (t < K_TAPS) sh[t] = 0;
    __syncthreads();
    atomicAdd(&ss[c0 + 0], s0); atomicAdd(&sq[c0 + 0], q0);
    atomicAdd(&ss[c0 + 1], s1); atomicAdd(&sq[c0 + 1], q1);
    atomicAdd(&ss[c0 + 2], s2); atomicAdd(&sq[c0 + 2], q2);
    atomicAdd(&ss[c0 + 3], s3); atomicAdd(&sq[c0 + 3], q3);

    // --- histogram ---
    for (long i = tid; i < nq; i += S) {
        int4 o = off4[i];
        atomicAdd(&sh[o.x & 7], 1);
        atomicAdd(&sh[o.y & 7], 1);
        atomicAdd(&sh[o.z & 7], 1);
        atomicAdd(&sh[o.w & 7], 1);
    }
    // tail elements
    if (blockIdx.x == 0 && t < (n & 3)) {
        const int* off = (const int*)off4;
        atomicAdd(&sh[off[(n & ~3) + t] & 7], 1);
    }
    __syncthreads();
    if (t < C_IN) {
        atomicAdd(&g_sum[t], ss[t]);
        atomicAdd(&g_sq[t], sq[t]);
    }
    if (t < K_TAPS) atomicAdd(&g_hist[t], sh[t]);
}

// ---------------- finalize BN params + exclusive scan of histogram ----------------
__global__ void k_mid(const float* __restrict__ gamma,
                      const float* __restrict__ beta, float inv_n) {
    int c = threadIdx.x;
    if (c < C_IN) {
        float mean = g_sum[c] * inv_n;
        float var  = g_sq[c] * inv_n - mean * mean;
        float sc   = gamma[c] * rsqrtf(var + 1e-5f);
        g_scale[c] = sc;
        g_shift[c] = beta[c] - mean * sc;
        g_sum[c] = 0.f;  // reset for next call (determinism across graph replays)
        g_sq[c]  = 0.f;
    }
    __syncthreads();
    if (c == 0) {
        int acc = 0;
        for (int t = 0; t < K_TAPS; t++) {
            g_base[t] = acc;
            g_cursor[t] = acc;
            acc += g_hist[t];
            g_hist[t] = 0;   // reset for next call
        }
        g_base[K_TAPS] = acc;
    }
}

// ---------------- tap-binning counting-sort scatter ----------------
__global__ void k_scat(const int4* __restrict__ off4, int nq, int n) {
    int i = blockIdx.x * blockDim.x + threadIdx.x;
    int S = gridDim.x * blockDim.x;
    int lane = threadIdx.x & 31;
    int nr = ((nq + 31) >> 5) << 5;
    for (; i < nr; i += S) {
        bool valid = (i < nq);
        int4 o = valid ? off4[i] : make_int4(0, 0, 0, 0);
        int base = i << 2;
#pragma unroll
        for (int t = 0; t < 4; t++) {
            unsigned mask = __ballot_sync(FULLMASK, valid);
            if (valid) {
                int tap = ((&o.x)[t]) & 7;
                unsigned peers = __match_any_sync(mask, tap);
                int leader = __ffs(peers) - 1;
                int rank = __popc(peers & ((1u << lane) - 1u));
                int pos0 = 0;
                if (lane == leader) pos0 = atomicAdd(&g_cursor[tap], __popc(peers));
                pos0 = __shfl_sync(mask, pos0, leader);
                g_perm[pos0 + rank] = base + t;
            }
        }
    }
    // tail
    if (blockIdx.x == 0 && threadIdx.x < (n & 3)) {
        const int* off = (const int*)off4;
        int e = (n & ~3) + threadIdx.x;
        int pos = atomicAdd(&g_cursor[off[e] & 7], 1);
        g_perm[pos] = e;
    }
}

// ---------------- main conv: warp-per-point-batch, weights in registers ----------------
__global__ void __launch_bounds__(256, 2)
k_conv(const float* __restrict__ f, const float* __restrict__ weight,
       const int* __restrict__ out_index, float* __restrict__ out,
       int n, int chunk) {
    __shared__ float2 sv[8][2][BATCH][C_IN];  // warp, dblbuf, point, channel (dup pair)
    int lane = threadIdx.x & 31;
    int wl = threadIdx.x >> 5;
    int w = (blockIdx.x * blockDim.x + threadIdx.x) >> 5;
    long startl = (long)w * chunk;
    if (startl >= n) return;
    int start = (int)startl;
    int end = (int)min((long)n, startl + chunk);

    float sc = g_scale[lane];
    float sh = g_shift[lane];

    int tap = -1;
    int nb = 0;
    unsigned long long wreg[32];

    int j = start, it = 0;
    while (j < end) {
        if (j >= nb) {
            do { tap++; nb = g_base[tap + 1]; } while (j >= nb);
            const float* wp = weight + ((tap << 5) << 6) + (lane << 1);
#pragma unroll
            for (int c = 0; c < 32; c++)
                wreg[c] = *(const unsigned long long*)(wp + (c << 6));
        }
        int m = min(min(BATCH, end - j), nb - j);

        // gather perm indices first (independent L2 loads)
        int idx[BATCH];
#pragma unroll
        for (int t = 0; t < BATCH; t++)
            if (t < m) idx[t] = g_perm[j + t];

        // independent row + feature gathers (MLP = 2*BATCH)
        int row[BATCH];
        float x[BATCH];
#pragma unroll
        for (int t = 0; t < BATCH; t++)
            if (t < m) {
                row[t] = out_index[idx[t]];
                x[t] = f[((long)idx[t] << 5) + lane];
            }

        int buf = it & 1;
#pragma unroll
        for (int t = 0; t < BATCH; t++)
            if (t < m) {
                float v = fmaxf(fmaf(x[t], sc, sh), 0.f);
                sv[wl][buf][t][lane] = make_float2(v, v);
            }
        __syncwarp();

#pragma unroll
        for (int t = 0; t < BATCH; t++)
            if (t < m) {
                const ulonglong2* vp = (const ulonglong2*)&sv[wl][buf][t][0];
                unsigned long long a0 = 0ull, a1 = 0ull;
#pragma unroll
                for (int k = 0; k < 8; k++) {
                    ulonglong2 q0 = vp[2 * k];      // (v4k dup | v4k+1 dup)
                    ulonglong2 q1 = vp[2 * k + 1];  // (v4k+2 dup | v4k+3 dup)
                    a0 = fma2(q0.x, wreg[4 * k + 0], a0);
                    a1 = fma2(q0.y, wreg[4 * k + 1], a1);
                    a0 = fma2(q1.x, wreg[4 * k + 2], a0);
                    a1 = fma2(q1.y, wreg[4 * k + 3], a1);
                }
                unsigned long long acc = add2(a0, a1);
                float rx, ry;
                asm("mov.b64 {%0, %1}, %2;" : "=f"(rx), "=f"(ry) : "l"(acc));
                red_add_v2(out + ((long)row[t] << 6) + (lane << 1), rx, ry);
            }
        j += m;
        it++;
    }
}

// ---------------- launch ----------------
extern "C" void kernel_launch(void* const* d_in, const int* in_sizes, int n_in,
                              void* d_out, int out_size) {
    const float* features = (const float*)d_in[0];
    const float* gamma    = (const float*)d_in[1];
    const float* beta     = (const float*)d_in[2];
    const float* weight   = (const float*)d_in[3];
    const int* out_index  = (const int*)d_in[4];
    const int* off_index  = (const int*)d_in[5];

    int n = in_sizes[0] / C_IN;
    int nq = n >> 2;

    k_pre<<<2048, 256>>>((float4*)d_out, (long)out_size / 4,
                         (const float4*)features, (long)n * C_IN / 4,
                         (const int4*)off_index, nq, n);
    k_mid<<<1, 64>>>(gamma, beta, 1.0f / (float)n);
    k_scat<<<1184, 256>>>((const int4*)off_index, nq, n);

    int nwarps = 296 * 8;  // persistent: 2 blocks/SM x 148 SMs x 8 warps
    int chunk = (n + nwarps - 1) / nwarps;
    if (chunk < 1) chunk = 1;
    k_conv<<<296, 256>>>(features, weight, out_index, (float*)d_out, n, chunk);
}

// round 4
// speedup vs baseline: 1.5845x; 1.0194x over previous
#include <cuda_runtime.h>

#define FULLMASK 0xffffffffu
#define C_IN 32
#define C_OUT 64
#define K_TAPS 8
#define NMAX 2001024
#define BSHIFT 9                     // 512 output rows per bucket
#define BROWS (1 << BSHIFT)
#define NBMAX ((NMAX >> BSHIFT) + 2)
#define NBINSMAX (NBMAX * 8)
#define BATCH 8

// ---------------- device scratch ----------------
__device__ float g_sum[C_IN];
__device__ float g_sq[C_IN];
__device__ float g_scale[C_IN];
__device__ float g_shift[C_IN];
__device__ int   g_hist2[NBINSMAX];
__device__ int   g_base2[NBINSMAX + 1];
__device__ int   g_cur2[NBINSMAX];
__device__ int   g_perm[NMAX];
__device__ int   g_prow[NMAX];

// ---------------- PTX helpers ----------------
__device__ __forceinline__ unsigned long long fma2(unsigned long long a,
                                                   unsigned long long b,
                                                   unsigned long long c) {
    unsigned long long d;
    asm("fma.rn.f32x2 %0, %1, %2, %3;" : "=l"(d) : "l"(a), "l"(b), "l"(c));
    return d;
}
__device__ __forceinline__ unsigned long long pk(float lo, float hi) {
    unsigned long long d;
    asm("mov.b64 %0, {%1, %2};" : "=l"(d) : "f"(lo), "f"(hi));
    return d;
}
__device__ __forceinline__ void upk(unsigned long long v, float& lo, float& hi) {
    asm("mov.b64 {%0, %1}, %2;" : "=f"(lo), "=f"(hi) : "l"(v));
}
__device__ __forceinline__ void red_add_v2(float* p, float a, float b) {
    asm volatile("red.global.add.v2.f32 [%0], {%1, %2};"
                 :: "l"(p), "f"(a), "f"(b) : "memory");
}

// ---------------- zero per-call state ----------------
__global__ void k_z(int nbins) {
    int i = blockIdx.x * blockDim.x + threadIdx.x;
    if (i < C_IN) { g_sum[i] = 0.f; g_sq[i] = 0.f; }
    int S = gridDim.x * blockDim.x;
    for (; i < nbins; i += S) g_hist2[i] = 0;
}

// ---------------- BN stats + 2-D (bucket,tap) histogram ----------------
__global__ void __launch_bounds__(256) k_pre(
    const float4* __restrict__ f4, long nf4,
    const int4* __restrict__ off4, const int4* __restrict__ oix4,
    int nq, int n) {
    long tid = blockIdx.x * (long)blockDim.x + threadIdx.x;
    long S = (long)gridDim.x * blockDim.x;   // 4*S % 32 == 0

    float s0 = 0, s1 = 0, s2 = 0, s3 = 0;
    float q0 = 0, q1 = 0, q2 = 0, q3 = 0;
    for (long i = tid; i < nf4; i += S) {
        float4 v = f4[i];
        s0 += v.x; q0 = fmaf(v.x, v.x, q0);
        s1 += v.y; q1 = fmaf(v.y, v.y, q1);
        s2 += v.z; q2 = fmaf(v.z, v.z, q2);
        s3 += v.w; q3 = fmaf(v.w, v.w, q3);
    }
    int c0 = (int)((tid * 4) & 31);

    __shared__ float ss[C_IN], sq[C_IN];
    int t = threadIdx.x;
    if (t < C_IN) { ss[t] = 0.f; sq[t] = 0.f; }
    __syncthreads();
    atomicAdd(&ss[c0 + 0], s0); atomicAdd(&sq[c0 + 0], q0);
    atomicAdd(&ss[c0 + 1], s1); atomicAdd(&sq[c0 + 1], q1);
    atomicAdd(&ss[c0 + 2], s2); atomicAdd(&sq[c0 + 2], q2);
    atomicAdd(&ss[c0 + 3], s3); atomicAdd(&sq[c0 + 3], q3);

    for (long i = tid; i < nq; i += S) {
        int4 o = off4[i];
        int4 r = oix4[i];
        atomicAdd(&g_hist2[((r.x >> BSHIFT) << 3) + (o.x & 7)], 1);
        atomicAdd(&g_hist2[((r.y >> BSHIFT) << 3) + (o.y & 7)], 1);
        atomicAdd(&g_hist2[((r.z >> BSHIFT) << 3) + (o.z & 7)], 1);
        atomicAdd(&g_hist2[((r.w >> BSHIFT) << 3) + (o.w & 7)], 1);
    }
    if (blockIdx.x == 0 && t < (n & 3)) {
        const int* off = (const int*)off4;
        const int* oix = (const int*)oix4;
        int e = (n & ~3) + t;
        atomicAdd(&g_hist2[((oix[e] >> BSHIFT) << 3) + (off[e] & 7)], 1);
    }
    __syncthreads();
    if (t < C_IN) {
        atomicAdd(&g_sum[t], ss[t]);
        atomicAdd(&g_sq[t], sq[t]);
    }
}

// ---------------- finalize BN params ----------------
__global__ void k_mid(const float* __restrict__ gamma,
                      const float* __restrict__ beta, float inv_n) {
    int c = threadIdx.x;
    if (c < C_IN) {
        float mean = g_sum[c] * inv_n;
        float var  = g_sq[c] * inv_n - mean * mean;
        float sc   = gamma[c] * rsqrtf(var + 1e-5f);
        g_scale[c] = sc;
        g_shift[c] = beta[c] - mean * sc;
    }
}

// ---------------- parallel exclusive scan over bins ----------------
__global__ void k_scan(int nbins) {
    __shared__ int warptot[32];
    int t = threadIdx.x;                     // 1024 threads
    int per = (nbins + 1023) >> 10;
    int b0 = t * per;
    int s = 0;
    for (int k = 0; k < per; k++) {
        int b = b0 + k;
        if (b < nbins) s += g_hist2[b];
    }
    int lane = t & 31, wid = t >> 5;
    int v = s;
#pragma unroll
    for (int d = 1; d < 32; d <<= 1) {
        int u = __shfl_up_sync(FULLMASK, v, d);
        if (lane >= d) v += u;
    }
    if (lane == 31) warptot[wid] = v;
    __syncthreads();
    if (wid == 0) {
        int w = warptot[lane];
#pragma unroll
        for (int d = 1; d < 32; d <<= 1) {
            int u = __shfl_up_sync(FULLMASK, w, d);
            if (lane >= d) w += u;
        }
        warptot[lane] = w;
    }
    __syncthreads();
    int run = v - s + (wid ? warptot[wid - 1] : 0);
    for (int k = 0; k < per; k++) {
        int b = b0 + k;
        if (b < nbins) {
            g_base2[b] = run;
            g_cur2[b] = run;
            run += g_hist2[b];
        }
    }
    if (t == 1023) g_base2[nbins] = run;
}

// ---------------- counting-sort scatter into (bucket,tap) bins ----------------
__global__ void k_scat(const int4* __restrict__ off4,
                       const int4* __restrict__ oix4, int nq, int n) {
    int i = blockIdx.x * blockDim.x + threadIdx.x;
    int S = gridDim.x * blockDim.x;
    for (; i < nq; i += S) {
        int4 o = off4[i];
        int4 r = oix4[i];
        int base = i << 2;
        {
            int pos = atomicAdd(&g_cur2[((r.x >> BSHIFT) << 3) + (o.x & 7)], 1);
            g_perm[pos] = base + 0; g_prow[pos] = r.x;
        }
        {
            int pos = atomicAdd(&g_cur2[((r.y >> BSHIFT) << 3) + (o.y & 7)], 1);
            g_perm[pos] = base + 1; g_prow[pos] = r.y;
        }
        {
            int pos = atomicAdd(&g_cur2[((r.z >> BSHIFT) << 3) + (o.z & 7)], 1);
            g_perm[pos] = base + 2; g_prow[pos] = r.z;
        }
        {
            int pos = atomicAdd(&g_cur2[((r.w >> BSHIFT) << 3) + (o.w & 7)], 1);
            g_perm[pos] = base + 3; g_prow[pos] = r.w;
        }
    }
    if (blockIdx.x == 0 && threadIdx.x < (n & 3)) {
        const int* off = (const int*)off4;
        const int* oix = (const int*)oix4;
        int e = (n & ~3) + threadIdx.x;
        int row = oix[e];
        int pos = atomicAdd(&g_cur2[((row >> BSHIFT) << 3) + (off[e] & 7)], 1);
        g_perm[pos] = e; g_prow[pos] = row;
    }
}

// ---------------- main conv: persistent CTA-per-bucket, warp = tap ----------------
__global__ void __launch_bounds__(256, 2)
k_conv(const float* __restrict__ f, const float* __restrict__ weight,
       float* __restrict__ out, int nb, int nrows) {
    __shared__ float sv[8][2][BATCH][C_IN];
    int lane = threadIdx.x & 31;
    int wl = threadIdx.x >> 5;          // warp id == tap id

    // tap weights, channel-paired: w0[k] = {w[2k][2l], w[2k+1][2l]}, w1 for col 2l+1
    unsigned long long w0[16], w1[16];
    {
        const float* wp = weight + (wl * C_IN) * C_OUT;
#pragma unroll
        for (int k = 0; k < 16; k++) {
            w0[k] = pk(wp[(2 * k) * C_OUT + 2 * lane],
                       wp[(2 * k + 1) * C_OUT + 2 * lane]);
            w1[k] = pk(wp[(2 * k) * C_OUT + 2 * lane + 1],
                       wp[(2 * k + 1) * C_OUT + 2 * lane + 1]);
        }
    }
    float sc = g_scale[lane];
    float sh = g_shift[lane];

    for (int b = blockIdx.x; b < nb; b += gridDim.x) {
        // zero this bucket's output region (stays dirty in L2 for the atomics)
        long r0 = (long)b << BSHIFT;
        long r1 = min((long)nrows, r0 + (long)BROWS);
        float4* oz = (float4*)(out + r0 * C_OUT);
        long n4 = (r1 - r0) * (C_OUT / 4);
        float4 z = make_float4(0.f, 0.f, 0.f, 0.f);
        for (long i = threadIdx.x; i < n4; i += 256) oz[i] = z;
        __syncthreads();

        int bin = b * 8 + wl;
        int j = g_base2[bin];
        int j1 = g_base2[bin + 1];
        int it = 0;
        while (j < j1) {
            int m = min(BATCH, j1 - j);
            int idx[BATCH], row[BATCH];
            float x[BATCH];
#pragma unroll
            for (int t = 0; t < BATCH; t++)
                if (t < m) idx[t] = g_perm[j + t];
#pragma unroll
            for (int t = 0; t < BATCH; t++)
                if (t < m) {
                    row[t] = g_prow[j + t];
                    x[t] = f[((long)idx[t] << 5) + lane];
                }
            int buf = it & 1;
#pragma unroll
            for (int t = 0; t < BATCH; t++)
                if (t < m) sv[wl][buf][t][lane] = fmaxf(fmaf(x[t], sc, sh), 0.f);
            __syncwarp();
#pragma unroll
            for (int t = 0; t < BATCH; t++)
                if (t < m) {
                    const ulonglong2* vp = (const ulonglong2*)&sv[wl][buf][t][0];
                    unsigned long long a0 = 0ull, a1 = 0ull;
#pragma unroll
                    for (int k = 0; k < 8; k++) {
                        ulonglong2 q = vp[k];   // {v4k,v4k+1 | v4k+2,v4k+3} broadcast
                        a0 = fma2(q.x, w0[2 * k], a0);
                        a1 = fma2(q.x, w1[2 * k], a1);
                        a0 = fma2(q.y, w0[2 * k + 1], a0);
                        a1 = fma2(q.y, w1[2 * k + 1], a1);
                    }
                    float e0, o0, e1, o1;
                    upk(a0, e0, o0);
                    upk(a1, e1, o1);
                    red_add_v2(out + ((long)row[t] << 6) + (lane << 1),
                               e0 + o0, e1 + o1);
                }
            j += m;
            it++;
        }
    }
}

// ---------------- launch ----------------
extern "C" void kernel_launch(void* const* d_in, const int* in_sizes, int n_in,
                              void* d_out, int out_size) {
    const float* features = (const float*)d_in[0];
    const float* gamma    = (const float*)d_in[1];
    const float* beta     = (const float*)d_in[2];
    const float* weight   = (const float*)d_in[3];
    const int* out_index  = (const int*)d_in[4];
    const int* off_index  = (const int*)d_in[5];

    int n = in_sizes[0] / C_IN;
    int nq = n >> 2;
    int nrows = out_size / C_OUT;
    int nb = (nrows + BROWS - 1) >> BSHIFT;
    int nbins = nb * 8;

    k_z<<<32, 1024>>>(nbins);
    k_pre<<<592, 256>>>((const float4*)features, (long)n * C_IN / 4,
                        (const int4*)off_index, (const int4*)out_index, nq, n);
    k_mid<<<1, 32>>>(gamma, beta, 1.0f / (float)n);
    k_scan<<<1, 1024>>>(nbins);
    k_scat<<<592, 256>>>((const int4*)off_index, (const int4*)out_index, nq, n);
    k_conv<<<296, 256>>>(features, weight, (float*)d_out, nb, nrows);
}

// round 5
// speedup vs baseline: 1.9368x; 1.2224x over previous
#include <cuda_runtime.h>

#define FULLMASK 0xffffffffu
#define C_IN 32
#define C_OUT 64
#define K_TAPS 8
#define NMAX 2001024
#define BSHIFT 10                    // 1024 output rows per bucket
#define BROWS (1 << BSHIFT)
#define NBMAX ((NMAX >> BSHIFT) + 2)
#define NBINSMAX (NBMAX * 8)
#define BATCH 8
#define IDXMASK 0x1FFFFF

// ---------------- device scratch ----------------
__device__ float g_sum[C_IN];
__device__ float g_sq[C_IN];
__device__ float g_scale[C_IN];
__device__ float g_shift[C_IN];
__device__ int   g_hist2[NBINSMAX];
__device__ int   g_base2[NBINSMAX + 1];
__device__ int   g_cur2[NBINSMAX];
__device__ int   g_perm[NMAX];
__device__ int   g_bsum[64];
__device__ int   g_bsumx[64];

// ---------------- PTX helpers ----------------
__device__ __forceinline__ unsigned long long fma2(unsigned long long a,
                                                   unsigned long long b,
                                                   unsigned long long c) {
    unsigned long long d;
    asm("fma.rn.f32x2 %0, %1, %2, %3;" : "=l"(d) : "l"(a), "l"(b), "l"(c));
    return d;
}
__device__ __forceinline__ unsigned long long pk(float lo, float hi) {
    unsigned long long d;
    asm("mov.b64 %0, {%1, %2};" : "=l"(d) : "f"(lo), "f"(hi));
    return d;
}
__device__ __forceinline__ void upk(unsigned long long v, float& lo, float& hi) {
    asm("mov.b64 {%0, %1}, %2;" : "=f"(lo), "=f"(hi) : "l"(v));
}
__device__ __forceinline__ void red_add_v2(float* p, float a, float b) {
    asm volatile("red.global.add.v2.f32 [%0], {%1, %2};"
                 :: "l"(p), "f"(a), "f"(b) : "memory");
}

// ---------------- BN stats + 2-D (bucket,tap) histogram ----------------
// g_hist2 / g_sum / g_sq are zero on entry: zero-initialized at module load,
// and re-zeroed by k_scanC / k_midB after use on every call (replay-safe).
__global__ void __launch_bounds__(256) k_pre(
    const float4* __restrict__ f4, long nf4,
    const int4* __restrict__ off4, const int4* __restrict__ oix4,
    int nq, int n) {
    long tid = blockIdx.x * (long)blockDim.x + threadIdx.x;
    long S = (long)gridDim.x * blockDim.x;   // 4*S % 32 == 0

    float s0 = 0, s1 = 0, s2 = 0, s3 = 0;
    float q0 = 0, q1 = 0, q2 = 0, q3 = 0;
    for (long i = tid; i < nf4; i += S) {
        float4 v = f4[i];
        s0 += v.x; q0 = fmaf(v.x, v.x, q0);
        s1 += v.y; q1 = fmaf(v.y, v.y, q1);
        s2 += v.z; q2 = fmaf(v.z, v.z, q2);
        s3 += v.w; q3 = fmaf(v.w, v.w, q3);
    }
    int c0 = (int)((tid * 4) & 31);

    __shared__ float ss[C_IN], sq[C_IN];
    int t = threadIdx.x;
    if (t < C_IN) { ss[t] = 0.f; sq[t] = 0.f; }
    __syncthreads();
    atomicAdd(&ss[c0 + 0], s0); atomicAdd(&sq[c0 + 0], q0);
    atomicAdd(&ss[c0 + 1], s1); atomicAdd(&sq[c0 + 1], q1);
    atomicAdd(&ss[c0 + 2], s2); atomicAdd(&sq[c0 + 2], q2);
    atomicAdd(&ss[c0 + 3], s3); atomicAdd(&sq[c0 + 3], q3);

    for (long i = tid; i < nq; i += S) {
        int4 o = off4[i];
        int4 r = oix4[i];
        atomicAdd(&g_hist2[((r.x >> BSHIFT) << 3) + (o.x & 7)], 1);
        atomicAdd(&g_hist2[((r.y >> BSHIFT) << 3) + (o.y & 7)], 1);
        atomicAdd(&g_hist2[((r.z >> BSHIFT) << 3) + (o.z & 7)], 1);
        atomicAdd(&g_hist2[((r.w >> BSHIFT) << 3) + (o.w & 7)], 1);
    }
    if (blockIdx.x == 0 && t < (n & 3)) {
        const int* off = (const int*)off4;
        const int* oix = (const int*)oix4;
        int e = (n & ~3) + t;
        atomicAdd(&g_hist2[((oix[e] >> BSHIFT) << 3) + (off[e] & 7)], 1);
    }
    __syncthreads();
    if (t < C_IN) {
        atomicAdd(&g_sum[t], ss[t]);
        atomicAdd(&g_sq[t], sq[t]);
    }
}

// ---------------- scan stage A: 64 block partial sums of 512-bin chunks ----------------
__global__ void k_scanA(int nbins) {
    __shared__ int wsum[16];
    int t = threadIdx.x;
    int b = blockIdx.x * 512 + t;
    int v = (b < nbins) ? g_hist2[b] : 0;
#pragma unroll
    for (int d = 16; d >= 1; d >>= 1) v += __shfl_down_sync(FULLMASK, v, d);
    if ((t & 31) == 0) wsum[t >> 5] = v;
    __syncthreads();
    if (t < 16) {
        int x = wsum[t];
#pragma unroll
        for (int d = 8; d >= 1; d >>= 1) x += __shfl_down_sync(0xffffu, x, d);
        if (t == 0) g_bsum[blockIdx.x] = x;
    }
}

// ---------------- BN finalize + scan of 64 block sums ----------------
__global__ void k_midB(const float* __restrict__ gamma,
                       const float* __restrict__ beta, float inv_n, int nbins) {
    __shared__ int w0tot;
    int t = threadIdx.x;   // 64
    if (t < C_IN) {
        float mean = g_sum[t] * inv_n;
        float var  = g_sq[t] * inv_n - mean * mean;
        float sc   = gamma[t] * rsqrtf(var + 1e-5f);
        g_scale[t] = sc;
        g_shift[t] = beta[t] - mean * sc;
        g_sum[t] = 0.f;   // reset for next replay
        g_sq[t]  = 0.f;
    }
    int v = g_bsum[t];
    int inc = v;
    int lane = t & 31;
#pragma unroll
    for (int d = 1; d < 32; d <<= 1) {
        int u = __shfl_up_sync(FULLMASK, inc, d);
        if (lane >= d) inc += u;
    }
    if (t == 31) w0tot = inc;
    __syncthreads();
    if (t >= 32) inc += w0tot;
    g_bsumx[t] = inc - v;
    if (t == 63) g_base2[nbins] = inc;
}

// ---------------- scan stage C: block-local exclusive scan + offset ----------------
__global__ void k_scanC(int nbins) {
    __shared__ int wtot[16];
    int t = threadIdx.x;
    int lane = t & 31, wid = t >> 5;
    int b = blockIdx.x * 512 + t;
    int v = (b < nbins) ? g_hist2[b] : 0;
    if (b < nbins) g_hist2[b] = 0;     // reset for next replay
    int inc = v;
#pragma unroll
    for (int d = 1; d < 32; d <<= 1) {
        int u = __shfl_up_sync(FULLMASK, inc, d);
        if (lane >= d) inc += u;
    }
    if (lane == 31) wtot[wid] = inc;
    __syncthreads();
    if (t < 16) {
        int x = wtot[t];
#pragma unroll
        for (int d = 1; d < 16; d <<= 1) {
            int u = __shfl_up_sync(0xffffu, x, d);
            if (t >= d) x += u;
        }
        wtot[t] = x;
    }
    __syncthreads();
    int exc = g_bsumx[blockIdx.x] + (wid ? wtot[wid - 1] : 0) + inc - v;
    if (b < nbins) { g_base2[b] = exc; g_cur2[b] = exc; }
}

// ---------------- counting-sort scatter: packed (rowlow<<21 | idx) ----------------
__global__ void k_scat(const int4* __restrict__ off4,
                       const int4* __restrict__ oix4, int nq, int n) {
    int i = blockIdx.x * blockDim.x + threadIdx.x;
    int S = gridDim.x * blockDim.x;
    for (; i < nq; i += S) {
        int4 o = off4[i];
        int4 r = oix4[i];
        int base = i << 2;
        {
            int pos = atomicAdd(&g_cur2[((r.x >> BSHIFT) << 3) + (o.x & 7)], 1);
            g_perm[pos] = ((r.x & (BROWS - 1)) << 21) | (base + 0);
        }
        {
            int pos = atomicAdd(&g_cur2[((r.y >> BSHIFT) << 3) + (o.y & 7)], 1);
            g_perm[pos] = ((r.y & (BROWS - 1)) << 21) | (base + 1);
        }
        {
            int pos = atomicAdd(&g_cur2[((r.z >> BSHIFT) << 3) + (o.z & 7)], 1);
            g_perm[pos] = ((r.z & (BROWS - 1)) << 21) | (base + 2);
        }
        {
            int pos = atomicAdd(&g_cur2[((r.w >> BSHIFT) << 3) + (o.w & 7)], 1);
            g_perm[pos] = ((r.w & (BROWS - 1)) << 21) | (base + 3);
        }
    }
    if (blockIdx.x == 0 && threadIdx.x < (n & 3)) {
        const int* off = (const int*)off4;
        const int* oix = (const int*)oix4;
        int e = (n & ~3) + threadIdx.x;
        int row = oix[e];
        int pos = atomicAdd(&g_cur2[((row >> BSHIFT) << 3) + (off[e] & 7)], 1);
        g_perm[pos] = ((row & (BROWS - 1)) << 21) | e;
    }
}

// ---------------- main conv: CTA-per-bucket, warp = tap, dist-2 pipeline ----------------
__global__ void __launch_bounds__(256, 2)
k_conv(const float* __restrict__ f, const float* __restrict__ weight,
       float* __restrict__ out, int nb, int nrows) {
    __shared__ float sv[8][2][BATCH][C_IN];
    int lane = threadIdx.x & 31;
    int wl = threadIdx.x >> 5;          // warp id == tap id

    // tap weights, channel-paired
    unsigned long long w0[16], w1[16];
    {
        const float* wp = weight + (wl * C_IN) * C_OUT;
#pragma unroll
        for (int k = 0; k < 16; k++) {
            w0[k] = pk(wp[(2 * k) * C_OUT + 2 * lane],
                       wp[(2 * k + 1) * C_OUT + 2 * lane]);
            w1[k] = pk(wp[(2 * k) * C_OUT + 2 * lane + 1],
                       wp[(2 * k + 1) * C_OUT + 2 * lane + 1]);
        }
    }
    float sc = g_scale[lane];
    float sh = g_shift[lane];

    for (int b = blockIdx.x; b < nb; b += gridDim.x) {
        // zero this bucket's output region (lines stay dirty in L2 for atomics)
        long r0 = (long)b << BSHIFT;
        long r1 = min((long)nrows, r0 + (long)BROWS);
        float4* oz = (float4*)(out + r0 * C_OUT);
        long n4 = (r1 - r0) * (C_OUT / 4);
        float4 z = make_float4(0.f, 0.f, 0.f, 0.f);
        for (long i = threadIdx.x; i < n4; i += 256) oz[i] = z;
        __syncthreads();

        int bin = (b << 3) + wl;
        int j = g_base2[bin];
        int j1 = g_base2[bin + 1];
        int rbase = b << BSHIFT;

        // ---- prologue: words(k), words(k+1), features(k) ----
        int m = min(BATCH, j1 - j);
        int wc[BATCH], wn[BATCH], wn2[BATCH];
        float x[BATCH];
#pragma unroll
        for (int t = 0; t < BATCH; t++)
            if (t < m) wc[t] = g_perm[j + t];
        int jn = j + m;
        int mn = min(BATCH, j1 - jn);
#pragma unroll
        for (int t = 0; t < BATCH; t++)
            if (t < mn) wn[t] = g_perm[jn + t];
#pragma unroll
        for (int t = 0; t < BATCH; t++)
            if (t < m) x[t] = f[((long)(wc[t] & IDXMASK) << 5) + lane];

        int it = 0;
        while (j < j1) {
            int buf = it & 1;
            // stage batch k (consumes x)
#pragma unroll
            for (int t = 0; t < BATCH; t++)
                if (t < m) sv[wl][buf][t][lane] = fmaxf(fmaf(x[t], sc, sh), 0.f);
            __syncwarp();

            // issue features(k+1) from resident words(k+1)
#pragma unroll
            for (int t = 0; t < BATCH; t++)
                if (t < mn) x[t] = f[((long)(wn[t] & IDXMASK) << 5) + lane];

            // issue words(k+2)
            int jn2 = jn + mn;
            int mn2 = min(BATCH, j1 - jn2);
#pragma unroll
            for (int t = 0; t < BATCH; t++)
                if (t < mn2) wn2[t] = g_perm[jn2 + t];

            // compute + reduce batch k
#pragma unroll
            for (int t = 0; t < BATCH; t++)
                if (t < m) {
                    const ulonglong2* vp = (const ulonglong2*)&sv[wl][buf][t][0];
                    unsigned long long a0 = 0ull, a1 = 0ull;
#pragma unroll
                    for (int k = 0; k < 8; k++) {
                        ulonglong2 q = vp[k];
                        a0 = fma2(q.x, w0[2 * k], a0);
                        a1 = fma2(q.x, w1[2 * k], a1);
                        a0 = fma2(q.y, w0[2 * k + 1], a0);
                        a1 = fma2(q.y, w1[2 * k + 1], a1);
                    }
                    float e0, o0, e1, o1;
                    upk(a0, e0, o0);
                    upk(a1, e1, o1);
                    int row = rbase + (wc[t] >> 21);
                    red_add_v2(out + ((long)row << 6) + (lane << 1),
                               e0 + o0, e1 + o1);
                }

            // rotate pipeline
#pragma unroll
            for (int t = 0; t < BATCH; t++) { wc[t] = wn[t]; wn[t] = wn2[t]; }
            j = jn; m = mn; jn = jn2; mn = mn2;
            it++;
        }
    }
}

// ---------------- launch ----------------
extern "C" void kernel_launch(void* const* d_in, const int* in_sizes, int n_in,
                              void* d_out, int out_size) {
    const float* features = (const float*)d_in[0];
    const float* gamma    = (const float*)d_in[1];
    const float* beta     = (const float*)d_in[2];
    const float* weight   = (const float*)d_in[3];
    const int* out_index  = (const int*)d_in[4];
    const int* off_index  = (const int*)d_in[5];

    int n = in_sizes[0] / C_IN;
    int nq = n >> 2;
    int nrows = out_size / C_OUT;
    int nb = (nrows + BROWS - 1) >> BSHIFT;
    int nbins = nb * 8;

    k_pre<<<592, 256>>>((const float4*)features, (long)n * C_IN / 4,
                        (const int4*)off_index, (const int4*)out_index, nq, n);
    k_scanA<<<64, 512>>>(nbins);
    k_midB<<<1, 64>>>(gamma, beta, 1.0f / (float)n, nbins);
    k_scanC<<<64, 512>>>(nbins);
    k_scat<<<592, 256>>>((const int4*)off_index, (const int4*)out_index, nq, n);
    k_conv<<<296, 256>>>(features, weight, (float*)d_out, nb, nrows);
}